// round 6
// baseline (speedup 1.0000x reference)
#include <cuda_runtime.h>
#include <math.h>

#define Bv 16
#define Tv 512
#define Sv 2048
#define Dv 768
#define SCH 64           // s-chunks per batch (fused pass)
#define RPB 32           // s-rows per block (Sv/SCH)
#define TCH 8            // t-rows per output block

// Scratch (__device__ globals: allocation-free rule)
__device__ float g_score[Bv * Sv];
__device__ float g_pctx[Bv * SCH * Dv];
__device__ float g_pmax[Bv * SCH];
__device__ float g_psum[Bv * SCH];
__device__ float g_ctx[Bv * Dv];
__device__ float g_cg[Bv];
__device__ float g_M[Bv];
__device__ float g_inv[Bv];

// ---------------------------------------------------------------------------
// K1: fused score + online-softmax partial context. grid=(SCH,B), 256 thr.
// Phase 1: 8 warps x 4 rows (one row per step, low regs) -> masked scores.
// Phase 2: 192 threads (float4 over D) accumulate exp-weighted enc rows
//          (lines hot in L1/L2 from phase 1).
// ---------------------------------------------------------------------------
__global__ void __launch_bounds__(256, 4)
k_score_ctx(const float* __restrict__ enc,
            const int* __restrict__ mask,
            const float* __restrict__ w_ptr) {
    int b = blockIdx.y, ch = blockIdx.x;
    int tid = threadIdx.x;
    int warp = tid >> 5, lane = tid & 31;

    __shared__ float ss[RPB];      // raw masked scores
    __shared__ float se[RPB];      // exp(score - lmax)

    const float4* w4 = reinterpret_cast<const float4*>(w_ptr + Dv);
    const float4* enc4 = reinterpret_cast<const float4*>(enc);

    // ---- phase 1: 4 rows per warp, one at a time ----
#pragma unroll
    for (int k = 0; k < 4; k++) {
        int r = warp * 4 + k;
        size_t bs = (size_t)b * Sv + ch * RPB + r;
        const float4* row = enc4 + bs * (Dv / 4);
        float a = 0.f;
#pragma unroll
        for (int i = 0; i < 6; i++) {
            float4 x  = row[lane + 32 * i];
            float4 ww = __ldg(&w4[lane + 32 * i]);
            a += x.x * ww.x + x.y * ww.y + x.z * ww.z + x.w * ww.w;
        }
#pragma unroll
        for (int o = 16; o; o >>= 1) a += __shfl_xor_sync(0xffffffffu, a, o);
        if (lane == 0) {
            float m = mask[bs] ? a : -1e9f;
            ss[r] = m;
            g_score[bs] = m;
        }
    }
    __syncthreads();

    // ---- chunk-local max / exp / sum (warp 0 over 32 rows) ----
    if (tid < 32) {
        float v = ss[tid];
        float m = v;
#pragma unroll
        for (int o = 16; o; o >>= 1) m = fmaxf(m, __shfl_xor_sync(0xffffffffu, m, o));
        float e = expf(v - m);
        se[tid] = e;
        float s = e;
#pragma unroll
        for (int o = 16; o; o >>= 1) s += __shfl_xor_sync(0xffffffffu, s, o);
        if (tid == 0) {
            g_pmax[b * SCH + ch] = m;
            g_psum[b * SCH + ch] = s;
        }
    }
    __syncthreads();

    // ---- phase 2: partial ctx ----
    if (tid < Dv / 4) {
        const float4* e4 = enc4 + ((size_t)b * Sv + ch * RPB) * (Dv / 4) + tid;
        float4 acc = make_float4(0.f, 0.f, 0.f, 0.f);
#pragma unroll 8
        for (int s = 0; s < RPB; s++) {
            float ws = se[s];
            float4 v = e4[(size_t)s * (Dv / 4)];
            acc.x += ws * v.x; acc.y += ws * v.y;
            acc.z += ws * v.z; acc.w += ws * v.w;
        }
        reinterpret_cast<float4*>(g_pctx)[(size_t)(b * SCH + ch) * (Dv / 4) + tid] = acc;
    }
}

// ---------------------------------------------------------------------------
// K2: per-batch combine of SCH chunks with softmax rescale.
// grid=B, 192 threads. Outputs g_ctx, g_cg, g_M, g_inv.
// ---------------------------------------------------------------------------
__global__ void k_reduce(const float* __restrict__ w_gen) {
    int b = blockIdx.x, tid = threadIdx.x;
    int warp = tid >> 5, lane = tid & 31;

    __shared__ float sf[SCH];
    __shared__ float smax, sS;
    __shared__ float r2[2], red[6];

    if (tid < 32) {
        float m = fmaxf(g_pmax[b * SCH + tid], g_pmax[b * SCH + tid + 32]);
#pragma unroll
        for (int o = 16; o; o >>= 1) m = fmaxf(m, __shfl_xor_sync(0xffffffffu, m, o));
        if (tid == 0) smax = m;
    }
    __syncthreads();
    float M = smax;

    if (tid < 64) {
        float f = expf(g_pmax[b * SCH + tid] - M);
        sf[tid] = f;
        float c = f * g_psum[b * SCH + tid];
#pragma unroll
        for (int o = 16; o; o >>= 1) c += __shfl_xor_sync(0xffffffffu, c, o);
        if (lane == 0) r2[warp] = c;
    }
    __syncthreads();
    if (tid == 0) sS = r2[0] + r2[1];
    __syncthreads();
    float inv = 1.f / sS;

    const float4* p4 = reinterpret_cast<const float4*>(g_pctx) + (size_t)b * SCH * (Dv / 4);
    float4 acc = make_float4(0.f, 0.f, 0.f, 0.f);
#pragma unroll 8
    for (int c = 0; c < SCH; c++) {
        float f = sf[c];
        float4 v = p4[(size_t)c * (Dv / 4) + tid];
        acc.x += f * v.x; acc.y += f * v.y;
        acc.z += f * v.z; acc.w += f * v.w;
    }
    acc.x *= inv; acc.y *= inv; acc.z *= inv; acc.w *= inv;
    reinterpret_cast<float4*>(g_ctx)[(size_t)b * (Dv / 4) + tid] = acc;

    float4 g = __ldg(reinterpret_cast<const float4*>(w_gen + Dv) + tid);
    float dot = acc.x * g.x + acc.y * g.y + acc.z * g.z + acc.w * g.w;
#pragma unroll
    for (int o = 16; o; o >>= 1) dot += __shfl_xor_sync(0xffffffffu, dot, o);
    if (lane == 0) red[warp] = dot;
    __syncthreads();
    if (tid == 0) {
        g_cg[b] = red[0] + red[1] + red[2] + red[3] + red[4] + red[5];
        g_M[b] = M;
        g_inv[b] = inv;
    }
}

// ---------------------------------------------------------------------------
// F: one block per (b, 8-t chunk). Normalize weights on the fly while
// staging into smem; broadcast via streaming stores; p_gen per-warp dots.
// Output layout: [pw (B*T*S)] [p_gen (B*T)] [context (B*T*D)]
// ---------------------------------------------------------------------------
__global__ void __launch_bounds__(256)
k_out(const float* __restrict__ dec,
      const float* __restrict__ w_gen,
      const float* __restrict__ b_gen,
      float* __restrict__ out) {
    int b = blockIdx.y;
    int t0 = blockIdx.x * TCH;
    int tid = threadIdx.x;                                // 256 threads
    int warp = tid >> 5, lane = tid & 31;

    __shared__ float sw[Sv];
    __shared__ float sc[Dv];
    __shared__ float spg[TCH];

    float M = g_M[b], inv = g_inv[b];
    float4* sw4 = reinterpret_cast<float4*>(sw);
    const float4* gs4 = reinterpret_cast<const float4*>(g_score) + (size_t)b * (Sv / 4);
#pragma unroll
    for (int i = 0; i < 2; i++) {
        float4 v = gs4[tid + 256 * i];
        float4 wv;
        wv.x = expf(v.x - M) * inv;
        wv.y = expf(v.y - M) * inv;
        wv.z = expf(v.z - M) * inv;
        wv.w = expf(v.w - M) * inv;
        sw4[tid + 256 * i] = wv;
    }
    float4* sc4 = reinterpret_cast<float4*>(sc);
    const float4* gc4 = reinterpret_cast<const float4*>(g_ctx) + (size_t)b * (Dv / 4);
    if (tid < Dv / 4) sc4[tid] = gc4[tid];

    // p_gen dec-dots: 8 warps, 1 t-row each
    {
        int tt = warp;
        size_t bt = (size_t)b * Tv + t0 + tt;
        const float4* drow = reinterpret_cast<const float4*>(dec) + bt * (Dv / 4);
        const float4* g4   = reinterpret_cast<const float4*>(w_gen);
        float acc = 0.f;
#pragma unroll
        for (int i = 0; i < 6; i++) {
            float4 a = __ldcs(&drow[lane + 32 * i]);
            float4 g = __ldg(&g4[lane + 32 * i]);
            acc += a.x * g.x + a.y * g.y + a.z * g.z + a.w * g.w;
        }
#pragma unroll
        for (int o = 16; o; o >>= 1) acc += __shfl_xor_sync(0xffffffffu, acc, o);
        if (lane == 0) spg[tt] = acc;
    }
    __syncthreads();

    float* ctx_base = out + (size_t)Bv * Tv * Sv + (size_t)Bv * Tv;
#pragma unroll
    for (int tt = 0; tt < TCH; tt++) {
        size_t bt = (size_t)b * Tv + t0 + tt;
        float4* pw4 = reinterpret_cast<float4*>(out) + bt * (Sv / 4);
#pragma unroll
        for (int i = 0; i < 2; i++)
            __stcs(&pw4[tid + 256 * i], sw4[tid + 256 * i]);
        if (tid < Dv / 4) {
            float4* c4 = reinterpret_cast<float4*>(ctx_base) + bt * (Dv / 4);
            __stcs(&c4[tid], sc4[tid]);
        }
    }

    if (tid < TCH) {
        float x = spg[tid] + g_cg[b] + __ldg(&b_gen[0]);
        out[(size_t)Bv * Tv * Sv + (size_t)b * Tv + t0 + tid] = 1.f / (1.f + expf(-x));
    }
}

// ---------------------------------------------------------------------------
extern "C" void kernel_launch(void* const* d_in, const int* in_sizes, int n_in,
                              void* d_out, int out_size) {
    const float* dec    = (const float*)d_in[0];
    const float* enc    = (const float*)d_in[1];
    const int*   mask   = (const int*)d_in[2];
    const float* w_ptr  = (const float*)d_in[3];
    // d_in[4] = b_ptr (zeros; cancels in softmax)
    const float* w_gen  = (const float*)d_in[5];
    const float* b_gen  = (const float*)d_in[6];
    float* out = (float*)d_out;

    dim3 g1(SCH, Bv);
    k_score_ctx<<<g1, 256>>>(enc, mask, w_ptr);
    k_reduce<<<Bv, 192>>>(w_gen);
    dim3 gf(Tv / TCH, Bv);
    k_out<<<gf, 256>>>(dec, w_gen, b_gen, out);
}

// round 7
// speedup vs baseline: 1.0317x; 1.0317x over previous
#include <cuda_runtime.h>
#include <math.h>

#define Bv 16
#define Tv 512
#define Sv 2048
#define Dv 768
#define SCH 64           // s-chunks per batch (fused pass)
#define RPB 32           // s-rows per block (Sv/SCH)
#define DCH 16           // dec-dot chunks per batch (32 t-rows each)
#define TCH 8            // t-rows per output block

// Scratch (__device__ globals: allocation-free rule)
__device__ float g_score[Bv * Sv];
__device__ float g_pctx[Bv * SCH * Dv];
__device__ float g_pmax[Bv * SCH];
__device__ float g_psum[Bv * SCH];
__device__ float g_ctx[Bv * Dv];
__device__ float g_cg[Bv];
__device__ float g_M[Bv];
__device__ float g_inv[Bv];
__device__ float g_pgd[Bv * Tv];   // dec[b,t] . w_gen[:D]

// ---------------------------------------------------------------------------
// K1: grid=(SCH+DCH, B), 256 thr.
//   blocks [0,SCH):   fused score + online-softmax partial context
//   blocks [SCH,..):  dec-dot blocks -> g_pgd (keeps K1 a pure-read kernel,
//                     strips the read stream out of the write-heavy F)
// ---------------------------------------------------------------------------
__global__ void __launch_bounds__(256, 4)
k_score_ctx(const float* __restrict__ enc,
            const int* __restrict__ mask,
            const float* __restrict__ w_ptr,
            const float* __restrict__ dec,
            const float* __restrict__ w_gen) {
    int b = blockIdx.y;
    int tid = threadIdx.x;
    int warp = tid >> 5, lane = tid & 31;

    if (blockIdx.x >= SCH) {
        // ---- dec-dot block: 8 warps x 4 t-rows ----
        int tch = blockIdx.x - SCH;
        const float4* g4 = reinterpret_cast<const float4*>(w_gen);
#pragma unroll
        for (int k = 0; k < 4; k++) {
            int t = tch * 32 + warp * 4 + k;
            size_t bt = (size_t)b * Tv + t;
            const float4* drow = reinterpret_cast<const float4*>(dec) + bt * (Dv / 4);
            float a = 0.f;
#pragma unroll
            for (int i = 0; i < 6; i++) {
                float4 x = drow[lane + 32 * i];
                float4 g = __ldg(&g4[lane + 32 * i]);
                a += x.x * g.x + x.y * g.y + x.z * g.z + x.w * g.w;
            }
#pragma unroll
            for (int o = 16; o; o >>= 1) a += __shfl_xor_sync(0xffffffffu, a, o);
            if (lane == 0) g_pgd[bt] = a;
        }
        return;
    }

    int ch = blockIdx.x;
    __shared__ float ss[RPB];
    __shared__ float se[RPB];

    const float4* w4 = reinterpret_cast<const float4*>(w_ptr + Dv);
    const float4* enc4 = reinterpret_cast<const float4*>(enc);

    // ---- phase 1: 4 rows per warp ----
#pragma unroll
    for (int k = 0; k < 4; k++) {
        int r = warp * 4 + k;
        size_t bs = (size_t)b * Sv + ch * RPB + r;
        const float4* row = enc4 + bs * (Dv / 4);
        float a = 0.f;
#pragma unroll
        for (int i = 0; i < 6; i++) {
            float4 x  = row[lane + 32 * i];
            float4 ww = __ldg(&w4[lane + 32 * i]);
            a += x.x * ww.x + x.y * ww.y + x.z * ww.z + x.w * ww.w;
        }
#pragma unroll
        for (int o = 16; o; o >>= 1) a += __shfl_xor_sync(0xffffffffu, a, o);
        if (lane == 0) {
            float m = mask[bs] ? a : -1e9f;
            ss[r] = m;
            g_score[bs] = m;
        }
    }
    __syncthreads();

    // ---- chunk-local max / exp / sum ----
    if (tid < 32) {
        float v = ss[tid];
        float m = v;
#pragma unroll
        for (int o = 16; o; o >>= 1) m = fmaxf(m, __shfl_xor_sync(0xffffffffu, m, o));
        float e = expf(v - m);
        se[tid] = e;
        float s = e;
#pragma unroll
        for (int o = 16; o; o >>= 1) s += __shfl_xor_sync(0xffffffffu, s, o);
        if (tid == 0) {
            g_pmax[b * SCH + ch] = m;
            g_psum[b * SCH + ch] = s;
        }
    }
    __syncthreads();

    // ---- phase 2: partial ctx (evict-first; lines are dead after this) ----
    if (tid < Dv / 4) {
        const float4* e4 = enc4 + ((size_t)b * Sv + ch * RPB) * (Dv / 4) + tid;
        float4 acc = make_float4(0.f, 0.f, 0.f, 0.f);
#pragma unroll 8
        for (int s = 0; s < RPB; s++) {
            float ws = se[s];
            float4 v = __ldcs(&e4[(size_t)s * (Dv / 4)]);
            acc.x += ws * v.x; acc.y += ws * v.y;
            acc.z += ws * v.z; acc.w += ws * v.w;
        }
        reinterpret_cast<float4*>(g_pctx)[(size_t)(b * SCH + ch) * (Dv / 4) + tid] = acc;
    }
}

// ---------------------------------------------------------------------------
// K2: per-batch combine of SCH chunks with softmax rescale.
// grid=B, 192 threads. Outputs g_ctx, g_cg, g_M, g_inv.
// ---------------------------------------------------------------------------
__global__ void k_reduce(const float* __restrict__ w_gen) {
    int b = blockIdx.x, tid = threadIdx.x;
    int warp = tid >> 5, lane = tid & 31;

    __shared__ float sf[SCH];
    __shared__ float smax, sS;
    __shared__ float r2[2], red[6];

    if (tid < 32) {
        float m = fmaxf(g_pmax[b * SCH + tid], g_pmax[b * SCH + tid + 32]);
#pragma unroll
        for (int o = 16; o; o >>= 1) m = fmaxf(m, __shfl_xor_sync(0xffffffffu, m, o));
        if (tid == 0) smax = m;
    }
    __syncthreads();
    float M = smax;

    if (tid < 64) {
        float f = expf(g_pmax[b * SCH + tid] - M);
        sf[tid] = f;
        float c = f * g_psum[b * SCH + tid];
#pragma unroll
        for (int o = 16; o; o >>= 1) c += __shfl_xor_sync(0xffffffffu, c, o);
        if (lane == 0) r2[warp] = c;
    }
    __syncthreads();
    if (tid == 0) sS = r2[0] + r2[1];
    __syncthreads();
    float inv = 1.f / sS;

    const float4* p4 = reinterpret_cast<const float4*>(g_pctx) + (size_t)b * SCH * (Dv / 4);
    float4 acc = make_float4(0.f, 0.f, 0.f, 0.f);
#pragma unroll 8
    for (int c = 0; c < SCH; c++) {
        float f = sf[c];
        float4 v = p4[(size_t)c * (Dv / 4) + tid];
        acc.x += f * v.x; acc.y += f * v.y;
        acc.z += f * v.z; acc.w += f * v.w;
    }
    acc.x *= inv; acc.y *= inv; acc.z *= inv; acc.w *= inv;
    reinterpret_cast<float4*>(g_ctx)[(size_t)b * (Dv / 4) + tid] = acc;

    float4 g = __ldg(reinterpret_cast<const float4*>(w_gen + Dv) + tid);
    float dot = acc.x * g.x + acc.y * g.y + acc.z * g.z + acc.w * g.w;
#pragma unroll
    for (int o = 16; o; o >>= 1) dot += __shfl_xor_sync(0xffffffffu, dot, o);
    if (lane == 0) red[warp] = dot;
    __syncthreads();
    if (tid == 0) {
        g_cg[b] = red[0] + red[1] + red[2] + red[3] + red[4] + red[5];
        g_M[b] = M;
        g_inv[b] = inv;
    }
}

// ---------------------------------------------------------------------------
// F: one block per (b, 8-t chunk). Pure-write kernel now: stage ~11KB from
// L2, then stream 88KB of stores. p_gen from precomputed g_pgd.
// Output layout: [pw (B*T*S)] [p_gen (B*T)] [context (B*T*D)]
// ---------------------------------------------------------------------------
__global__ void __launch_bounds__(256)
k_out(const float* __restrict__ b_gen,
      float* __restrict__ out) {
    int b = blockIdx.y;
    int t0 = blockIdx.x * TCH;
    int tid = threadIdx.x;                                // 256 threads

    __shared__ float sw[Sv];
    __shared__ float sc[Dv];

    float M = g_M[b], inv = g_inv[b];
    float4* sw4 = reinterpret_cast<float4*>(sw);
    const float4* gs4 = reinterpret_cast<const float4*>(g_score) + (size_t)b * (Sv / 4);
#pragma unroll
    for (int i = 0; i < 2; i++) {
        float4 v = gs4[tid + 256 * i];
        float4 wv;
        wv.x = expf(v.x - M) * inv;
        wv.y = expf(v.y - M) * inv;
        wv.z = expf(v.z - M) * inv;
        wv.w = expf(v.w - M) * inv;
        sw4[tid + 256 * i] = wv;
    }
    float4* sc4 = reinterpret_cast<float4*>(sc);
    const float4* gc4 = reinterpret_cast<const float4*>(g_ctx) + (size_t)b * (Dv / 4);
    if (tid < Dv / 4) sc4[tid] = gc4[tid];
    __syncthreads();

    float* ctx_base = out + (size_t)Bv * Tv * Sv + (size_t)Bv * Tv;
#pragma unroll
    for (int tt = 0; tt < TCH; tt++) {
        size_t bt = (size_t)b * Tv + t0 + tt;
        float4* pw4 = reinterpret_cast<float4*>(out) + bt * (Sv / 4);
#pragma unroll
        for (int i = 0; i < 2; i++)
            __stcs(&pw4[tid + 256 * i], sw4[tid + 256 * i]);
        if (tid < Dv / 4) {
            float4* c4 = reinterpret_cast<float4*>(ctx_base) + bt * (Dv / 4);
            __stcs(&c4[tid], sc4[tid]);
        }
    }

    if (tid < TCH) {
        size_t bt = (size_t)b * Tv + t0 + tid;
        float x = g_pgd[bt] + g_cg[b] + __ldg(&b_gen[0]);
        out[(size_t)Bv * Tv * Sv + bt] = 1.f / (1.f + expf(-x));
    }
}

// ---------------------------------------------------------------------------
extern "C" void kernel_launch(void* const* d_in, const int* in_sizes, int n_in,
                              void* d_out, int out_size) {
    const float* dec    = (const float*)d_in[0];
    const float* enc    = (const float*)d_in[1];
    const int*   mask   = (const int*)d_in[2];
    const float* w_ptr  = (const float*)d_in[3];
    // d_in[4] = b_ptr (zeros; cancels in softmax)
    const float* w_gen  = (const float*)d_in[5];
    const float* b_gen  = (const float*)d_in[6];
    float* out = (float*)d_out;

    dim3 g1(SCH + DCH, Bv);
    k_score_ctx<<<g1, 256>>>(enc, mask, w_ptr, dec, w_gen);
    k_reduce<<<Bv, 192>>>(w_gen);
    dim3 gf(Tv / TCH, Bv);
    k_out<<<gf, 256>>>(b_gen, out);
}

// round 8
// speedup vs baseline: 1.3462x; 1.3049x over previous
#include <cuda_runtime.h>
#include <math.h>

#define Bv 16
#define Tv 512
#define Sv 2048
#define Dv 768
#define SCH 16           // ctx chunks per batch (128 rows per block)
#define RPB 128          // s-rows per ctx block
#define RPW 16           // s-rows per warp
#define DCH 16           // dec-dot chunks per batch (32 t-rows each)
#define TCH 8            // t-rows per output block

// Scratch (__device__ globals: allocation-free rule)
__device__ float g_score[Bv * Sv];
__device__ float g_pctx[Bv * SCH * Dv];
__device__ float g_pmax[Bv * SCH];
__device__ float g_psum[Bv * SCH];
__device__ float g_ctx[Bv * Dv];
__device__ float g_cg[Bv];
__device__ float g_M[Bv];
__device__ float g_inv[Bv];
__device__ float g_pgd[Bv * Tv];   // dec[b,t] . w_gen[:D]

// ---------------------------------------------------------------------------
// K1: grid=(SCH+DCH, B), 256 thr.
//   blocks [0,SCH):  single-pass flash-style score+context. Each warp holds
//                    the current enc row in registers, computes its score,
//                    and online-accumulates e*row into a register partial.
//   blocks [SCH,..): dec-dot blocks -> g_pgd.
// ---------------------------------------------------------------------------
__global__ void __launch_bounds__(256)
k_score_ctx(const float* __restrict__ enc,
            const int* __restrict__ mask,
            const float* __restrict__ w_ptr,
            const float* __restrict__ dec,
            const float* __restrict__ w_gen) {
    int b = blockIdx.y;
    int tid = threadIdx.x;
    int warp = tid >> 5, lane = tid & 31;

    if (blockIdx.x >= SCH) {
        // ---- dec-dot block: 8 warps x 4 t-rows ----
        int tch = blockIdx.x - SCH;
        const float4* g4 = reinterpret_cast<const float4*>(w_gen);
#pragma unroll
        for (int k = 0; k < 4; k++) {
            int t = tch * 32 + warp * 4 + k;
            size_t bt = (size_t)b * Tv + t;
            const float4* drow = reinterpret_cast<const float4*>(dec) + bt * (Dv / 4);
            float a = 0.f;
#pragma unroll
            for (int i = 0; i < 6; i++) {
                float4 x = drow[lane + 32 * i];
                float4 g = __ldg(&g4[lane + 32 * i]);
                a += x.x * g.x + x.y * g.y + x.z * g.z + x.w * g.w;
            }
#pragma unroll
            for (int o = 16; o; o >>= 1) a += __shfl_xor_sync(0xffffffffu, a, o);
            if (lane == 0) g_pgd[bt] = a;
        }
        return;
    }

    // ---- ctx block ----
    int ch = blockIdx.x;
    const float4* enc4 = reinterpret_cast<const float4*>(enc);

    // w_ptr[D:2D] in registers
    float4 wr[6];
#pragma unroll
    for (int i = 0; i < 6; i++)
        wr[i] = __ldg(&reinterpret_cast<const float4*>(w_ptr + Dv)[lane + 32 * i]);

    size_t base = (size_t)b * Sv + ch * RPB + warp * RPW;
    const float4* rp = enc4 + base * (Dv / 4);

    float4 acc[6];
#pragma unroll
    for (int i = 0; i < 6; i++) acc[i] = make_float4(0.f, 0.f, 0.f, 0.f);
    float m_run = -1e9f, s_run = 0.f;

#pragma unroll 2
    for (int k = 0; k < RPW; k++) {
        float4 x[6];
#pragma unroll
        for (int i = 0; i < 6; i++)
            x[i] = __ldcs(&rp[(size_t)k * (Dv / 4) + lane + 32 * i]);

        float a = 0.f;
#pragma unroll
        for (int i = 0; i < 6; i++)
            a += x[i].x * wr[i].x + x[i].y * wr[i].y
               + x[i].z * wr[i].z + x[i].w * wr[i].w;
#pragma unroll
        for (int o = 16; o; o >>= 1) a += __shfl_xor_sync(0xffffffffu, a, o);

        float ms = mask[base + k] ? a : -1e9f;
        if (lane == 0) g_score[base + k] = ms;

        float mnew = fmaxf(m_run, ms);
        float corr = expf(m_run - mnew);
        float e    = expf(ms - mnew);
        s_run = s_run * corr + e;
#pragma unroll
        for (int i = 0; i < 6; i++) {
            acc[i].x = acc[i].x * corr + e * x[i].x;
            acc[i].y = acc[i].y * corr + e * x[i].y;
            acc[i].z = acc[i].z * corr + e * x[i].z;
            acc[i].w = acc[i].w * corr + e * x[i].w;
        }
        m_run = mnew;
    }

    // ---- block combine: 8 warp partials -> one chunk partial ----
    __shared__ float4 sacc[8][Dv / 4];   // 24 KB
    __shared__ float sm[8], ssum[8], sf[8];
#pragma unroll
    for (int i = 0; i < 6; i++) sacc[warp][lane + 32 * i] = acc[i];
    if (lane == 0) { sm[warp] = m_run; ssum[warp] = s_run; }
    __syncthreads();

    float m_b = sm[0];
#pragma unroll
    for (int w = 1; w < 8; w++) m_b = fmaxf(m_b, sm[w]);
    if (tid < 8) sf[tid] = expf(sm[tid] - m_b);
    __syncthreads();

    if (tid < Dv / 4) {
        float4 v = make_float4(0.f, 0.f, 0.f, 0.f);
#pragma unroll
        for (int w = 0; w < 8; w++) {
            float f = sf[w];
            float4 p = sacc[w][tid];
            v.x += f * p.x; v.y += f * p.y; v.z += f * p.z; v.w += f * p.w;
        }
        reinterpret_cast<float4*>(g_pctx)[(size_t)(b * SCH + ch) * (Dv / 4) + tid] = v;
    }
    if (tid == 0) {
        float s = 0.f;
#pragma unroll
        for (int w = 0; w < 8; w++) s += sf[w] * ssum[w];
        g_pmax[b * SCH + ch] = m_b;
        g_psum[b * SCH + ch] = s;
    }
}

// ---------------------------------------------------------------------------
// K2: per-batch combine of SCH chunks with softmax rescale.
// grid=B, 192 threads. Outputs g_ctx, g_cg, g_M, g_inv.
// ---------------------------------------------------------------------------
__global__ void k_reduce(const float* __restrict__ w_gen) {
    int b = blockIdx.x, tid = threadIdx.x;
    int warp = tid >> 5, lane = tid & 31;

    __shared__ float sf[SCH];
    __shared__ float smax, sS;
    __shared__ float red[6];

    if (tid < 32) {
        float m = (tid < SCH) ? g_pmax[b * SCH + tid] : -3e38f;
#pragma unroll
        for (int o = 16; o; o >>= 1) m = fmaxf(m, __shfl_xor_sync(0xffffffffu, m, o));
        if (tid == 0) smax = m;
    }
    __syncthreads();
    float M = smax;

    if (tid < 32) {
        float c = 0.f;
        if (tid < SCH) {
            float f = expf(g_pmax[b * SCH + tid] - M);
            sf[tid] = f;
            c = f * g_psum[b * SCH + tid];
        }
#pragma unroll
        for (int o = 16; o; o >>= 1) c += __shfl_xor_sync(0xffffffffu, c, o);
        if (tid == 0) sS = c;
    }
    __syncthreads();
    float inv = 1.f / sS;

    const float4* p4 = reinterpret_cast<const float4*>(g_pctx) + (size_t)b * SCH * (Dv / 4);
    float4 acc = make_float4(0.f, 0.f, 0.f, 0.f);
#pragma unroll
    for (int c = 0; c < SCH; c++) {
        float f = sf[c];
        float4 v = p4[(size_t)c * (Dv / 4) + tid];
        acc.x += f * v.x; acc.y += f * v.y;
        acc.z += f * v.z; acc.w += f * v.w;
    }
    acc.x *= inv; acc.y *= inv; acc.z *= inv; acc.w *= inv;
    reinterpret_cast<float4*>(g_ctx)[(size_t)b * (Dv / 4) + tid] = acc;

    float4 g = __ldg(reinterpret_cast<const float4*>(w_gen + Dv) + tid);
    float dot = acc.x * g.x + acc.y * g.y + acc.z * g.z + acc.w * g.w;
#pragma unroll
    for (int o = 16; o; o >>= 1) dot += __shfl_xor_sync(0xffffffffu, dot, o);
    if (lane == 0) red[warp] = dot;
    __syncthreads();
    if (tid == 0) {
        g_cg[b] = red[0] + red[1] + red[2] + red[3] + red[4] + red[5];
        g_M[b] = M;
        g_inv[b] = inv;
    }
}

// ---------------------------------------------------------------------------
// F: one block per (b, 8-t chunk). Pure-write kernel: stage ~11KB from L2,
// stream ~88KB of stores. p_gen from precomputed g_pgd.
// Output layout: [pw (B*T*S)] [p_gen (B*T)] [context (B*T*D)]
// ---------------------------------------------------------------------------
__global__ void __launch_bounds__(256)
k_out(const float* __restrict__ b_gen,
      float* __restrict__ out) {
    int b = blockIdx.y;
    int t0 = blockIdx.x * TCH;
    int tid = threadIdx.x;

    __shared__ float sw[Sv];
    __shared__ float sc[Dv];

    float M = g_M[b], inv = g_inv[b];
    float4* sw4 = reinterpret_cast<float4*>(sw);
    const float4* gs4 = reinterpret_cast<const float4*>(g_score) + (size_t)b * (Sv / 4);
#pragma unroll
    for (int i = 0; i < 2; i++) {
        float4 v = gs4[tid + 256 * i];
        float4 wv;
        wv.x = expf(v.x - M) * inv;
        wv.y = expf(v.y - M) * inv;
        wv.z = expf(v.z - M) * inv;
        wv.w = expf(v.w - M) * inv;
        sw4[tid + 256 * i] = wv;
    }
    float4* sc4 = reinterpret_cast<float4*>(sc);
    const float4* gc4 = reinterpret_cast<const float4*>(g_ctx) + (size_t)b * (Dv / 4);
    if (tid < Dv / 4) sc4[tid] = gc4[tid];
    __syncthreads();

    float* ctx_base = out + (size_t)Bv * Tv * Sv + (size_t)Bv * Tv;
#pragma unroll
    for (int tt = 0; tt < TCH; tt++) {
        size_t bt = (size_t)b * Tv + t0 + tt;
        float4* pw4 = reinterpret_cast<float4*>(out) + bt * (Sv / 4);
#pragma unroll
        for (int i = 0; i < 2; i++)
            __stcs(&pw4[tid + 256 * i], sw4[tid + 256 * i]);
        if (tid < Dv / 4) {
            float4* c4 = reinterpret_cast<float4*>(ctx_base) + bt * (Dv / 4);
            __stcs(&c4[tid], sc4[tid]);
        }
    }

    if (tid < TCH) {
        size_t bt = (size_t)b * Tv + t0 + tid;
        float x = g_pgd[bt] + g_cg[b] + __ldg(&b_gen[0]);
        out[(size_t)Bv * Tv * Sv + bt] = 1.f / (1.f + expf(-x));
    }
}

// ---------------------------------------------------------------------------
extern "C" void kernel_launch(void* const* d_in, const int* in_sizes, int n_in,
                              void* d_out, int out_size) {
    const float* dec    = (const float*)d_in[0];
    const float* enc    = (const float*)d_in[1];
    const int*   mask   = (const int*)d_in[2];
    const float* w_ptr  = (const float*)d_in[3];
    // d_in[4] = b_ptr (zeros; cancels in softmax)
    const float* w_gen  = (const float*)d_in[5];
    const float* b_gen  = (const float*)d_in[6];
    float* out = (float*)d_out;

    dim3 g1(SCH + DCH, Bv);
    k_score_ctx<<<g1, 256>>>(enc, mask, w_ptr, dec, w_gen);
    k_reduce<<<Bv, 192>>>(w_gen);
    dim3 gf(Tv / TCH, Bv);
    k_out<<<gf, 256>>>(b_gen, out);
}